// round 10
// baseline (speedup 1.0000x reference)
#include <cuda_runtime.h>

#define HWD   21952              // 28^3
#define BSTR  2809856            // 128*HWD
#define NG    87808              // 4*HWD = 256 windows * 343
#define ATT_SCALE 0.17677669529663687f

// dynamic smem for attention: q,k,v [32][343] + probs [64][343] + rinv[64] + osp[343]
#define ATTN_SMEM_FLOATS (3*10976 + 64*343 + 64 + 343)
#define ATTN_SMEM_BYTES  (ATTN_SMEM_FLOATS * 4)

// ---------------- scratch (device globals: the sanctioned workaround) ----------------
__device__ float g_qkv[384u * 87808u];     // rows 0..127 q, 128..255 k, 256..383 relu(v)
__device__ float g_attn[128u * 87808u];    // attention output, layout [C][B*spatial]
__device__ float g_yb[128u * 87808u];      // conv3d output, layout [C][B*spatial]
__device__ float g_bn[512];                // [0:128) sc1 [128:256) sh1 [256:384) sc2 [384:512) sh2

__device__ __forceinline__ float silu_f(float v) {
    return v / (1.0f + __expf(-v));
}

// ===================== BN stats on input x (B,C,H,W,D) =====================
__global__ __launch_bounds__(256) void bn_stats_in_kernel(const float* __restrict__ x,
                                                          const float* __restrict__ gamma,
                                                          const float* __restrict__ beta)
{
    int c = blockIdx.x;
    float s = 0.f, s2 = 0.f;
    for (int b = 0; b < 4; ++b) {
        const float* p = x + (size_t)b * BSTR + (size_t)c * HWD;
        for (int i = threadIdx.x; i < HWD; i += 256) {
            float v = p[i];
            s += v; s2 += v * v;
        }
    }
    __shared__ float rs[256], rq[256];
    rs[threadIdx.x] = s; rq[threadIdx.x] = s2;
    __syncthreads();
    for (int o = 128; o > 0; o >>= 1) {
        if (threadIdx.x < o) {
            rs[threadIdx.x] += rs[threadIdx.x + o];
            rq[threadIdx.x] += rq[threadIdx.x + o];
        }
        __syncthreads();
    }
    if (threadIdx.x == 0) {
        const float inv = 1.f / (4.f * (float)HWD);
        float m   = rs[0] * inv;
        float var = rq[0] * inv - m * m;
        float r   = rsqrtf(var + 1e-6f);
        float sc  = gamma[c] * r;
        g_bn[c]       = sc;
        g_bn[128 + c] = beta[c] - m * sc;
    }
}

// ===================== BN stats on conv output g_yb [C][NG] =====================
__global__ __launch_bounds__(256) void bn_stats_y_kernel(const float* __restrict__ gamma,
                                                         const float* __restrict__ beta)
{
    int c = blockIdx.x;
    const float* p = g_yb + (size_t)c * NG;
    float s = 0.f, s2 = 0.f;
    for (int i = threadIdx.x; i < NG; i += 256) {
        float v = p[i];
        s += v; s2 += v * v;
    }
    __shared__ float rs[256], rq[256];
    rs[threadIdx.x] = s; rq[threadIdx.x] = s2;
    __syncthreads();
    for (int o = 128; o > 0; o >>= 1) {
        if (threadIdx.x < o) {
            rs[threadIdx.x] += rs[threadIdx.x + o];
            rq[threadIdx.x] += rq[threadIdx.x + o];
        }
        __syncthreads();
    }
    if (threadIdx.x == 0) {
        const float inv = 1.f / (float)NG;
        float m   = rs[0] * inv;
        float var = rq[0] * inv - m * m;
        float r   = rsqrtf(var + 1e-6f);
        float sc  = gamma[c] * r;
        g_bn[256 + c] = sc;
        g_bn[384 + c] = beta[c] - m * sc;
    }
}

// ===================== QKV GEMM: [384x128] @ bn(windowed x)[128 x 87808] =====================
// column n = w*343 + l ; window w = b0*64 + a*16 + b*4 + c ; spatial h = i*4+a (dilated)
__global__ __launch_bounds__(256) void qkv_gemm_kernel(const float* __restrict__ x,
                                                       const float* __restrict__ w_qk,
                                                       const float* __restrict__ w_v)
{
    __shared__ __align__(16) float As[16 * 64];
    __shared__ __align__(16) float Bs[16 * 64];
    __shared__ int colbase[64];
    int tid = threadIdx.x;
    int n0 = blockIdx.x * 64;
    int m0 = blockIdx.y * 64;
    if (tid < 64) {
        int n = n0 + tid;
        int w = n / 343;
        int l = n - w * 343;
        int b0 = w >> 6, rem = w & 63;
        int wa = rem >> 4, wb = (rem >> 2) & 3, wc = rem & 3;
        int i = l / 49; int r2 = l - i * 49;
        int j = r2 / 7; int kx = r2 - j * 7;
        colbase[tid] = b0 * BSTR + (i*4 + wa) * 784 + (j*4 + wb) * 28 + (kx*4 + wc);
    }
    __syncthreads();
    int ty = tid >> 4, tx = tid & 15;
    int am = tid >> 2, ak = (tid & 3) << 2;
    int bk = tid >> 4, bc0 = (tid & 15) << 2;
    const float* wrow = (m0 < 256) ? (w_qk + (size_t)(m0 + am) * 128)
                                   : (w_v  + (size_t)(m0 - 256 + am) * 128);
    float acc[4][4];
#pragma unroll
    for (int r = 0; r < 4; ++r)
#pragma unroll
        for (int c = 0; c < 4; ++c) acc[r][c] = 0.f;

    for (int k0 = 0; k0 < 128; k0 += 16) {
        float4 av = *(const float4*)(wrow + k0 + ak);
        As[(ak+0)*64 + am] = av.x;
        As[(ak+1)*64 + am] = av.y;
        As[(ak+2)*64 + am] = av.z;
        As[(ak+3)*64 + am] = av.w;
        int kg = k0 + bk;
        float scv = g_bn[kg], shv = g_bn[128 + kg];
        const float* xk = x + (size_t)kg * HWD;
#pragma unroll
        for (int j = 0; j < 4; ++j)
            Bs[bk*64 + bc0 + j] = fmaf(xk[colbase[bc0 + j]], scv, shv);
        __syncthreads();
#pragma unroll
        for (int kk = 0; kk < 16; ++kk) {
            float4 a4 = *(const float4*)&As[kk*64 + ty*4];
            float4 b4 = *(const float4*)&Bs[kk*64 + tx*4];
            float ar[4] = {a4.x, a4.y, a4.z, a4.w};
            float br[4] = {b4.x, b4.y, b4.z, b4.w};
#pragma unroll
            for (int r = 0; r < 4; ++r)
#pragma unroll
                for (int c = 0; c < 4; ++c)
                    acc[r][c] = fmaf(ar[r], br[c], acc[r][c]);
        }
        __syncthreads();
    }
    bool dorelu = (m0 >= 256);
#pragma unroll
    for (int r = 0; r < 4; ++r) {
        int m = m0 + ty*4 + r;
        float4 o;
        o.x = acc[r][0]; o.y = acc[r][1]; o.z = acc[r][2]; o.w = acc[r][3];
        if (dorelu) {
            o.x = fmaxf(o.x, 0.f); o.y = fmaxf(o.y, 0.f);
            o.z = fmaxf(o.z, 0.f); o.w = fmaxf(o.w, 0.f);
        }
        *(float4*)(g_qkv + (size_t)m * NG + n0 + tx*4) = o;
    }
}

// ===================== Attention: one block per (window, head) =====================
__global__ __launch_bounds__(256) void attn_kernel()
{
    extern __shared__ float sm[];
    float* qs   = sm;                  // [32][343]  q[d][l]
    float* ks   = sm + 10976;          // [32][343]
    float* vs   = sm + 2 * 10976;      // [32][343]
    float* ps   = sm + 3 * 10976;      // [64][343]  scores->probs for row group
    float* rinv = ps + 64 * 343;       // [64]
    int*   osp  = (int*)(rinv + 64);   // [343] output spatial offsets

    int tid = threadIdx.x;
    int w = blockIdx.x >> 2, h = blockIdx.x & 3;
    int b0 = w >> 6, rem = w & 63;
    int wa = rem >> 4, wb = (rem >> 2) & 3, wc = rem & 3;

    int gq = (h * 32) * NG + w * 343;
    for (int idx = tid; idx < 10976; idx += 256) {
        int d = idx / 343, l = idx - d * 343;
        int g = gq + d * NG + l;
        qs[idx] = g_qkv[g];
        ks[idx] = g_qkv[g + 128 * NG];
        vs[idx] = g_qkv[g + 256 * NG];
    }
    for (int l = tid; l < 343; l += 256) {
        int i = l / 49, r2 = l - i * 49;
        int j = r2 / 7, kx = r2 - j * 7;
        osp[l] = b0 * HWD + (i*4 + wa) * 784 + (j*4 + wb) * 28 + (kx*4 + wc);
    }
    __syncthreads();

    int ty   = tid >> 4, tx  = tid & 15;   // phase S layout
    int lane = tid & 31, wp  = tid >> 5;   // softmax layout
    int ty32 = tid >> 3, tx8 = tid & 7;    // phase O layout

    for (int g = 0; g < 6; ++g) {
        int l0 = g * 64;
        int lidx[4];
#pragma unroll
        for (int r = 0; r < 4; ++r) lidx[r] = min(l0 + ty*4 + r, 342);

        // ---- S = scale * Q^T K : 4 rows x 8 cols per thread, 3 col passes ----
        for (int pass = 0; pass < 3; ++pass) {
            int mc[8]; bool mok[8];
#pragma unroll
            for (int c = 0; c < 8; ++c) {
                int mr = pass*128 + tx + c*16;
                mok[c] = (mr < 343);
                mc[c] = mok[c] ? mr : 342;
            }
            float accs[4][8];
#pragma unroll
            for (int r = 0; r < 4; ++r)
#pragma unroll
                for (int c = 0; c < 8; ++c) accs[r][c] = 0.f;
#pragma unroll 4
            for (int d = 0; d < 32; ++d) {
                float qv[4], kv[8];
#pragma unroll
                for (int r = 0; r < 4; ++r) qv[r] = qs[d*343 + lidx[r]];
#pragma unroll
                for (int c = 0; c < 8; ++c) kv[c] = ks[d*343 + mc[c]];
#pragma unroll
                for (int r = 0; r < 4; ++r)
#pragma unroll
                    for (int c = 0; c < 8; ++c)
                        accs[r][c] = fmaf(qv[r], kv[c], accs[r][c]);
            }
#pragma unroll
            for (int r = 0; r < 4; ++r)
#pragma unroll
                for (int c = 0; c < 8; ++c)
                    if (mok[c]) ps[(ty*4 + r)*343 + mc[c]] = accs[r][c] * ATT_SCALE;
        }
        __syncthreads();

        // ---- softmax per row (warp per 8 rows) ----
        for (int r8 = 0; r8 < 8; ++r8) {
            int rr = wp * 8 + r8;
            float mx = -1e30f;
            for (int m = lane; m < 343; m += 32) mx = fmaxf(mx, ps[rr*343 + m]);
#pragma unroll
            for (int o = 16; o > 0; o >>= 1) mx = fmaxf(mx, __shfl_xor_sync(0xffffffffu, mx, o));
            float s = 0.f;
            for (int m = lane; m < 343; m += 32) {
                float p = __expf(ps[rr*343 + m] - mx);
                ps[rr*343 + m] = p;
                s += p;
            }
#pragma unroll
            for (int o = 16; o > 0; o >>= 1) s += __shfl_xor_sync(0xffffffffu, s, o);
            if (lane == 0) rinv[rr] = 1.f / s;
        }
        __syncthreads();

        // ---- O = P V^T : 2 rows x 4 d per thread ----
        float acco[2][4];
#pragma unroll
        for (int r = 0; r < 2; ++r)
#pragma unroll
            for (int j = 0; j < 4; ++j) acco[r][j] = 0.f;
        int rr0 = ty32 * 2;
        int d0  = tx8 * 4;
#pragma unroll 2
        for (int m = 0; m < 343; ++m) {
            float p0 = ps[rr0*343 + m];
            float p1 = ps[(rr0+1)*343 + m];
            float vv[4];
#pragma unroll
            for (int j = 0; j < 4; ++j) vv[j] = vs[(d0 + j)*343 + m];
#pragma unroll
            for (int j = 0; j < 4; ++j) {
                acco[0][j] = fmaf(p0, vv[j], acco[0][j]);
                acco[1][j] = fmaf(p1, vv[j], acco[1][j]);
            }
        }
#pragma unroll
        for (int r = 0; r < 2; ++r) {
            int l = l0 + rr0 + r;
            if (l < 343) {
                float ri = rinv[rr0 + r];
                int sp = osp[l];
#pragma unroll
                for (int j = 0; j < 4; ++j)
                    g_attn[(size_t)(h*32 + d0 + j) * NG + sp] = acco[r][j] * ri;
            }
        }
        __syncthreads();  // ps reused next group
    }
}

// ===================== conv3d 3x3x3 (128->128) as implicit GEMM =====================
// K ordered tap-major: k = t*128 + c  (each 16-chunk has fixed tap)
__global__ __launch_bounds__(256) void conv3d_kernel(const float* __restrict__ w_cl)
{
    __shared__ __align__(16) float As[16 * 64];
    __shared__ __align__(16) float Bs[16 * 64];
    __shared__ int   nn[64];
    __shared__ short shh[64], sww[64], sdd[64];
    int tid = threadIdx.x;
    int n0 = blockIdx.x * 64;
    int m0 = blockIdx.y * 64;
    if (tid < 64) {
        int n = n0 + tid;
        int b = n / HWD; int sp = n - b * HWD;
        int hh = sp / 784; int r2 = sp - hh * 784;
        int ww = r2 / 28;  int dd = r2 - ww * 28;
        nn[tid] = n; shh[tid] = (short)hh; sww[tid] = (short)ww; sdd[tid] = (short)dd;
    }
    __syncthreads();
    int ty = tid >> 4, tx = tid & 15;
    int am = tid >> 2, ak = (tid & 3) << 2;
    int bk = tid >> 4, bc0 = (tid & 15) << 2;
    float acc[4][4];
#pragma unroll
    for (int r = 0; r < 4; ++r)
#pragma unroll
        for (int c = 0; c < 4; ++c) acc[r][c] = 0.f;

    for (int k0 = 0; k0 < 3456; k0 += 16) {
        int t  = k0 >> 7;         // tap index 0..26
        int c0 = k0 & 127;
        int dh1 = t / 9 - 1;
        int r3  = t % 9;
        int dw1 = r3 / 3 - 1;
        int dd1 = r3 % 3 - 1;
        int delta = dh1 * 784 + dw1 * 28 + dd1;
#pragma unroll
        for (int i = 0; i < 4; ++i)
            As[(ak + i)*64 + am] = w_cl[(size_t)(m0 + am) * 3456 + (c0 + ak + i) * 27 + t];
        const float* xr = g_attn + (size_t)(c0 + bk) * NG;
#pragma unroll
        for (int j = 0; j < 4; ++j) {
            int bc = bc0 + j;
            bool ok = (unsigned)(shh[bc] + dh1) < 28u &&
                      (unsigned)(sww[bc] + dw1) < 28u &&
                      (unsigned)(sdd[bc] + dd1) < 28u;
            Bs[bk*64 + bc] = ok ? xr[nn[bc] + delta] : 0.f;
        }
        __syncthreads();
#pragma unroll
        for (int kk = 0; kk < 16; ++kk) {
            float4 a4 = *(const float4*)&As[kk*64 + ty*4];
            float4 b4 = *(const float4*)&Bs[kk*64 + tx*4];
            float ar[4] = {a4.x, a4.y, a4.z, a4.w};
            float br[4] = {b4.x, b4.y, b4.z, b4.w};
#pragma unroll
            for (int r = 0; r < 4; ++r)
#pragma unroll
                for (int c = 0; c < 4; ++c)
                    acc[r][c] = fmaf(ar[r], br[c], acc[r][c]);
        }
        __syncthreads();
    }
#pragma unroll
    for (int r = 0; r < 4; ++r) {
        int m = m0 + ty*4 + r;
        float4 o;
        o.x = acc[r][0]; o.y = acc[r][1]; o.z = acc[r][2]; o.w = acc[r][3];
        *(float4*)(g_yb + (size_t)m * NG + n0 + tx*4) = o;
    }
}

// ===================== final: out = x + w_proj @ (attn + silu(bn(yb))) =====================
__global__ __launch_bounds__(256) void final_kernel(const float* __restrict__ x,
                                                    const float* __restrict__ w_proj,
                                                    float* __restrict__ out)
{
    __shared__ __align__(16) float As[16 * 64];
    __shared__ __align__(16) float Bs[16 * 64];
    int tid = threadIdx.x;
    int n0 = blockIdx.x * 64;
    int m0 = blockIdx.y * 64;
    int ty = tid >> 4, tx = tid & 15;
    int am = tid >> 2, ak = (tid & 3) << 2;
    int bk = tid >> 4, bc0 = (tid & 15) << 2;
    float acc[4][4];
#pragma unroll
    for (int r = 0; r < 4; ++r)
#pragma unroll
        for (int c = 0; c < 4; ++c) acc[r][c] = 0.f;

    for (int k0 = 0; k0 < 128; k0 += 16) {
        float4 av = *(const float4*)(w_proj + (size_t)(m0 + am) * 128 + k0 + ak);
        As[(ak+0)*64 + am] = av.x;
        As[(ak+1)*64 + am] = av.y;
        As[(ak+2)*64 + am] = av.z;
        As[(ak+3)*64 + am] = av.w;
        int i = k0 + bk;
        float sc = g_bn[256 + i], sh = g_bn[384 + i];
        float4 ya = *(const float4*)(g_yb   + (size_t)i * NG + n0 + bc0);
        float4 aa = *(const float4*)(g_attn + (size_t)i * NG + n0 + bc0);
        float4 tb;
        tb.x = aa.x + silu_f(fmaf(ya.x, sc, sh));
        tb.y = aa.y + silu_f(fmaf(ya.y, sc, sh));
        tb.z = aa.z + silu_f(fmaf(ya.z, sc, sh));
        tb.w = aa.w + silu_f(fmaf(ya.w, sc, sh));
        *(float4*)&Bs[bk*64 + bc0] = tb;
        __syncthreads();
#pragma unroll
        for (int kk = 0; kk < 16; ++kk) {
            float4 a4 = *(const float4*)&As[kk*64 + ty*4];
            float4 b4 = *(const float4*)&Bs[kk*64 + tx*4];
            float ar[4] = {a4.x, a4.y, a4.z, a4.w};
            float br[4] = {b4.x, b4.y, b4.z, b4.w};
#pragma unroll
            for (int r = 0; r < 4; ++r)
#pragma unroll
                for (int c = 0; c < 4; ++c)
                    acc[r][c] = fmaf(ar[r], br[c], acc[r][c]);
        }
        __syncthreads();
    }
    int b = n0 / HWD;                 // 21952 % 64 == 0 -> whole tile in one batch
    int sp = n0 - b * HWD + tx * 4;
#pragma unroll
    for (int r = 0; r < 4; ++r) {
        int m = m0 + ty*4 + r;
        size_t o = (size_t)b * BSTR + (size_t)m * HWD + sp;
        float4 xv = *(const float4*)(x + o);
        float4 ov;
        ov.x = xv.x + acc[r][0];
        ov.y = xv.y + acc[r][1];
        ov.z = xv.z + acc[r][2];
        ov.w = xv.w + acc[r][3];
        *(float4*)(out + o) = ov;
    }
}

// ===================== launch =====================
extern "C" void kernel_launch(void* const* d_in, const int* in_sizes, int n_in,
                              void* d_out, int out_size)
{
    const float* x      = (const float*)d_in[0];
    const float* g_in   = (const float*)d_in[1];
    const float* b_in   = (const float*)d_in[2];
    const float* w_qk   = (const float*)d_in[3];
    const float* w_v    = (const float*)d_in[4];
    const float* w_cl   = (const float*)d_in[5];
    const float* g_cl   = (const float*)d_in[6];
    const float* b_cl   = (const float*)d_in[7];
    const float* w_proj = (const float*)d_in[8];
    float* out = (float*)d_out;

    cudaFuncSetAttribute(attn_kernel, cudaFuncAttributeMaxDynamicSharedMemorySize,
                         ATTN_SMEM_BYTES);

    bn_stats_in_kernel<<<128, 256>>>(x, g_in, b_in);
    qkv_gemm_kernel<<<dim3(1372, 6), 256>>>(x, w_qk, w_v);
    attn_kernel<<<1024, 256, ATTN_SMEM_BYTES>>>();
    conv3d_kernel<<<dim3(1372, 2), 256>>>(w_cl);
    bn_stats_y_kernel<<<128, 256>>>(g_cl, b_cl);
    final_kernel<<<dim3(1372, 2), 256>>>(x, w_proj, out);
}

// round 11
// speedup vs baseline: 1.5857x; 1.5857x over previous
#include <cuda_runtime.h>

#define HWD   21952              // 28^3
#define BSTR  2809856            // 128*HWD
#define NG    87808              // 4*HWD = 256 windows * 343
#define ATT_SCALE 0.17677669529663687f

// dynamic smem for attention: q,k,v [32][343] + probs [64][343] + rinv[64] + osp[343]
#define ATTN_SMEM_FLOATS (3*10976 + 64*343 + 64 + 343)
#define ATTN_SMEM_BYTES  (ATTN_SMEM_FLOATS * 4)

// ---------------- scratch (device globals: the sanctioned workaround) ----------------
__device__ float g_qkv[384u * 87808u];     // rows 0..127 q, 128..255 k, 256..383 relu(v)
__device__ float g_attn[128u * 87808u];    // attention output, layout [C][B*spatial]
__device__ float g_yb[128u * 87808u];      // conv3d output, layout [C][B*spatial]
__device__ float g_wt[3456 * 128];         // conv weight transposed: [k = t*128+c][m]
__device__ float g_bn[512];                // [0:128) sc1 [128:256) sh1 [256:384) sc2 [384:512) sh2

__device__ __forceinline__ float silu_f(float v) {
    return v / (1.0f + __expf(-v));
}

// ===================== BN stats on input x (B,C,H,W,D) =====================
__global__ __launch_bounds__(256) void bn_stats_in_kernel(const float* __restrict__ x,
                                                          const float* __restrict__ gamma,
                                                          const float* __restrict__ beta)
{
    int c = blockIdx.x;
    float s = 0.f, s2 = 0.f;
    for (int b = 0; b < 4; ++b) {
        const float* p = x + (size_t)b * BSTR + (size_t)c * HWD;
        for (int i = threadIdx.x; i < HWD; i += 256) {
            float v = p[i];
            s += v; s2 += v * v;
        }
    }
    __shared__ float rs[256], rq[256];
    rs[threadIdx.x] = s; rq[threadIdx.x] = s2;
    __syncthreads();
    for (int o = 128; o > 0; o >>= 1) {
        if (threadIdx.x < o) {
            rs[threadIdx.x] += rs[threadIdx.x + o];
            rq[threadIdx.x] += rq[threadIdx.x + o];
        }
        __syncthreads();
    }
    if (threadIdx.x == 0) {
        const float inv = 1.f / (4.f * (float)HWD);
        float m   = rs[0] * inv;
        float var = rq[0] * inv - m * m;
        float r   = rsqrtf(var + 1e-6f);
        float sc  = gamma[c] * r;
        g_bn[c]       = sc;
        g_bn[128 + c] = beta[c] - m * sc;
    }
}

// ===================== BN stats on conv output g_yb [C][NG] =====================
__global__ __launch_bounds__(256) void bn_stats_y_kernel(const float* __restrict__ gamma,
                                                         const float* __restrict__ beta)
{
    int c = blockIdx.x;
    const float* p = g_yb + (size_t)c * NG;
    float s = 0.f, s2 = 0.f;
    for (int i = threadIdx.x; i < NG; i += 256) {
        float v = p[i];
        s += v; s2 += v * v;
    }
    __shared__ float rs[256], rq[256];
    rs[threadIdx.x] = s; rq[threadIdx.x] = s2;
    __syncthreads();
    for (int o = 128; o > 0; o >>= 1) {
        if (threadIdx.x < o) {
            rs[threadIdx.x] += rs[threadIdx.x + o];
            rq[threadIdx.x] += rq[threadIdx.x + o];
        }
        __syncthreads();
    }
    if (threadIdx.x == 0) {
        const float inv = 1.f / (float)NG;
        float m   = rs[0] * inv;
        float var = rq[0] * inv - m * m;
        float r   = rsqrtf(var + 1e-6f);
        float sc  = gamma[c] * r;
        g_bn[256 + c] = sc;
        g_bn[384 + c] = beta[c] - m * sc;
    }
}

// ===================== weight transpose: g_wt[(t*128+c)*128 + m] = w_cl[m][c][t] =====================
__global__ __launch_bounds__(256) void wt_kernel(const float* __restrict__ w_cl)
{
    int idx = blockIdx.x * 256 + threadIdx.x;   // 3456*128 = 442368 total
    if (idx < 3456 * 128) {
        int k = idx >> 7;        // 0..3455
        int m = idx & 127;
        int t = k >> 7;          // tap 0..26
        int c = k & 127;
        g_wt[idx] = w_cl[(size_t)m * 3456 + c * 27 + t];
    }
}

// ===================== QKV GEMM: [384x128] @ bn(windowed x)[128 x 87808] =====================
// column n = w*343 + l ; window w = b0*64 + a*16 + b*4 + c ; spatial h = i*4+a (dilated)
__global__ __launch_bounds__(256) void qkv_gemm_kernel(const float* __restrict__ x,
                                                       const float* __restrict__ w_qk,
                                                       const float* __restrict__ w_v)
{
    __shared__ __align__(16) float As[16 * 64];
    __shared__ __align__(16) float Bs[16 * 64];
    __shared__ int colbase[64];
    int tid = threadIdx.x;
    int n0 = blockIdx.x * 64;
    int m0 = blockIdx.y * 64;
    if (tid < 64) {
        int n = n0 + tid;
        int w = n / 343;
        int l = n - w * 343;
        int b0 = w >> 6, rem = w & 63;
        int wa = rem >> 4, wb = (rem >> 2) & 3, wc = rem & 3;
        int i = l / 49; int r2 = l - i * 49;
        int j = r2 / 7; int kx = r2 - j * 7;
        colbase[tid] = b0 * BSTR + (i*4 + wa) * 784 + (j*4 + wb) * 28 + (kx*4 + wc);
    }
    __syncthreads();
    int ty = tid >> 4, tx = tid & 15;
    int am = tid >> 2, ak = (tid & 3) << 2;
    int bk = tid >> 4, bc0 = (tid & 15) << 2;
    const float* wrow = (m0 < 256) ? (w_qk + (size_t)(m0 + am) * 128)
                                   : (w_v  + (size_t)(m0 - 256 + am) * 128);
    float acc[4][4];
#pragma unroll
    for (int r = 0; r < 4; ++r)
#pragma unroll
        for (int c = 0; c < 4; ++c) acc[r][c] = 0.f;

    for (int k0 = 0; k0 < 128; k0 += 16) {
        float4 av = *(const float4*)(wrow + k0 + ak);
        As[(ak+0)*64 + am] = av.x;
        As[(ak+1)*64 + am] = av.y;
        As[(ak+2)*64 + am] = av.z;
        As[(ak+3)*64 + am] = av.w;
        int kg = k0 + bk;
        float scv = g_bn[kg], shv = g_bn[128 + kg];
        const float* xk = x + (size_t)kg * HWD;
#pragma unroll
        for (int j = 0; j < 4; ++j)
            Bs[bk*64 + bc0 + j] = fmaf(xk[colbase[bc0 + j]], scv, shv);
        __syncthreads();
#pragma unroll
        for (int kk = 0; kk < 16; ++kk) {
            float4 a4 = *(const float4*)&As[kk*64 + ty*4];
            float4 b4 = *(const float4*)&Bs[kk*64 + tx*4];
            float ar[4] = {a4.x, a4.y, a4.z, a4.w};
            float br[4] = {b4.x, b4.y, b4.z, b4.w};
#pragma unroll
            for (int r = 0; r < 4; ++r)
#pragma unroll
                for (int c = 0; c < 4; ++c)
                    acc[r][c] = fmaf(ar[r], br[c], acc[r][c]);
        }
        __syncthreads();
    }
    bool dorelu = (m0 >= 256);
#pragma unroll
    for (int r = 0; r < 4; ++r) {
        int m = m0 + ty*4 + r;
        float4 o;
        o.x = acc[r][0]; o.y = acc[r][1]; o.z = acc[r][2]; o.w = acc[r][3];
        if (dorelu) {
            o.x = fmaxf(o.x, 0.f); o.y = fmaxf(o.y, 0.f);
            o.z = fmaxf(o.z, 0.f); o.w = fmaxf(o.w, 0.f);
        }
        *(float4*)(g_qkv + (size_t)m * NG + n0 + tx*4) = o;
    }
}

// ===================== Attention: one block per (window, head) =====================
__global__ __launch_bounds__(256) void attn_kernel()
{
    extern __shared__ float sm[];
    float* qs   = sm;                  // [32][343]  q[d][l]
    float* ks   = sm + 10976;          // [32][343]
    float* vs   = sm + 2 * 10976;      // [32][343]
    float* ps   = sm + 3 * 10976;      // [64][343]  scores->probs for row group
    float* rinv = ps + 64 * 343;       // [64]
    int*   osp  = (int*)(rinv + 64);   // [343] output spatial offsets

    int tid = threadIdx.x;
    int w = blockIdx.x >> 2, h = blockIdx.x & 3;
    int b0 = w >> 6, rem = w & 63;
    int wa = rem >> 4, wb = (rem >> 2) & 3, wc = rem & 3;

    int gq = (h * 32) * NG + w * 343;
    for (int idx = tid; idx < 10976; idx += 256) {
        int d = idx / 343, l = idx - d * 343;
        int g = gq + d * NG + l;
        qs[idx] = g_qkv[g];
        ks[idx] = g_qkv[g + 128 * NG];
        vs[idx] = g_qkv[g + 256 * NG];
    }
    for (int l = tid; l < 343; l += 256) {
        int i = l / 49, r2 = l - i * 49;
        int j = r2 / 7, kx = r2 - j * 7;
        osp[l] = b0 * HWD + (i*4 + wa) * 784 + (j*4 + wb) * 28 + (kx*4 + wc);
    }
    __syncthreads();

    int ty   = tid >> 4, tx  = tid & 15;   // phase S layout
    int lane = tid & 31, wp  = tid >> 5;   // softmax layout
    int ty32 = tid >> 3, tx8 = tid & 7;    // phase O layout

    for (int g = 0; g < 6; ++g) {
        int l0 = g * 64;
        int lidx[4];
#pragma unroll
        for (int r = 0; r < 4; ++r) lidx[r] = min(l0 + ty*4 + r, 342);

        // ---- S = scale * Q^T K : 4 rows x 8 cols per thread, 3 col passes ----
        for (int pass = 0; pass < 3; ++pass) {
            int mc[8]; bool mok[8];
#pragma unroll
            for (int c = 0; c < 8; ++c) {
                int mr = pass*128 + tx + c*16;
                mok[c] = (mr < 343);
                mc[c] = mok[c] ? mr : 342;
            }
            float accs[4][8];
#pragma unroll
            for (int r = 0; r < 4; ++r)
#pragma unroll
                for (int c = 0; c < 8; ++c) accs[r][c] = 0.f;
#pragma unroll 4
            for (int d = 0; d < 32; ++d) {
                float qv[4], kv[8];
#pragma unroll
                for (int r = 0; r < 4; ++r) qv[r] = qs[d*343 + lidx[r]];
#pragma unroll
                for (int c = 0; c < 8; ++c) kv[c] = ks[d*343 + mc[c]];
#pragma unroll
                for (int r = 0; r < 4; ++r)
#pragma unroll
                    for (int c = 0; c < 8; ++c)
                        accs[r][c] = fmaf(qv[r], kv[c], accs[r][c]);
            }
#pragma unroll
            for (int r = 0; r < 4; ++r)
#pragma unroll
                for (int c = 0; c < 8; ++c)
                    if (mok[c]) ps[(ty*4 + r)*343 + mc[c]] = accs[r][c] * ATT_SCALE;
        }
        __syncthreads();

        // ---- softmax per row (warp per 8 rows) ----
        for (int r8 = 0; r8 < 8; ++r8) {
            int rr = wp * 8 + r8;
            float mx = -1e30f;
            for (int m = lane; m < 343; m += 32) mx = fmaxf(mx, ps[rr*343 + m]);
#pragma unroll
            for (int o = 16; o > 0; o >>= 1) mx = fmaxf(mx, __shfl_xor_sync(0xffffffffu, mx, o));
            float s = 0.f;
            for (int m = lane; m < 343; m += 32) {
                float p = __expf(ps[rr*343 + m] - mx);
                ps[rr*343 + m] = p;
                s += p;
            }
#pragma unroll
            for (int o = 16; o > 0; o >>= 1) s += __shfl_xor_sync(0xffffffffu, s, o);
            if (lane == 0) rinv[rr] = 1.f / s;
        }
        __syncthreads();

        // ---- O = P V^T : 2 rows x 4 d per thread ----
        float acco[2][4];
#pragma unroll
        for (int r = 0; r < 2; ++r)
#pragma unroll
            for (int j = 0; j < 4; ++j) acco[r][j] = 0.f;
        int rr0 = ty32 * 2;
        int d0  = tx8 * 4;
#pragma unroll 2
        for (int m = 0; m < 343; ++m) {
            float p0 = ps[rr0*343 + m];
            float p1 = ps[(rr0+1)*343 + m];
            float vv[4];
#pragma unroll
            for (int j = 0; j < 4; ++j) vv[j] = vs[(d0 + j)*343 + m];
#pragma unroll
            for (int j = 0; j < 4; ++j) {
                acco[0][j] = fmaf(p0, vv[j], acco[0][j]);
                acco[1][j] = fmaf(p1, vv[j], acco[1][j]);
            }
        }
#pragma unroll
        for (int r = 0; r < 2; ++r) {
            int l = l0 + rr0 + r;
            if (l < 343) {
                float ri = rinv[rr0 + r];
                int sp = osp[l];
#pragma unroll
                for (int j = 0; j < 4; ++j)
                    g_attn[(size_t)(h*32 + d0 + j) * NG + sp] = acco[r][j] * ri;
            }
        }
        __syncthreads();  // ps reused next group
    }
}

// ===================== conv3d 3x3x3 (128->128), 128x128 tile, 8x8 micro-tile =====================
// K ordered tap-major: k = t*128 + c ; tap fixed within each 16-chunk.
__global__ __launch_bounds__(256, 2) void conv3d_kernel()
{
    __shared__ __align__(16) float As[16][128];
    __shared__ __align__(16) float Bs[16][128];
    __shared__ int shh[128], sww[128], sdd[128];

    int tid = threadIdx.x;
    int n0 = blockIdx.x * 128;

    if (tid < 128) {
        int n = n0 + tid;
        int b = n / HWD; int sp = n - b * HWD;
        int hh = sp / 784; int r2 = sp - hh * 784;
        int ww = r2 / 28;  int dd = r2 - ww * 28;
        shh[tid] = hh; sww[tid] = ww; sdd[tid] = dd;
    }
    __syncthreads();

    int ty = tid >> 4, tx = tid & 15;       // compute map: m = ty*8+r, n = n0+tx*8+c
    int kkb = tid >> 4;                     // B fill: row kkb, cols jb..jb+7
    int jb  = (tid & 15) << 3;
    // A fill: float4 f = tid + i*256 ; kk = f>>5 ; col = (f&31)*4
    int akk0 = tid >> 5,        acol0 = (tid & 31) << 2;
    int akk1 = (tid + 256) >> 5, acol1 = acol0;

    float4 aR0, aR1;
    float  bR[8];

    // ---- prefetch k0 = 0 ----
    {
        const int k0 = 0;
        aR0 = *(const float4*)(g_wt + (size_t)(k0 + akk0) * 128 + acol0);
        aR1 = *(const float4*)(g_wt + (size_t)(k0 + akk1) * 128 + acol1);
        int t = 0;
        int dh = -1, dw = -1, dz = -1;
        (void)t;
        int delta = dh * 784 + dw * 28 + dz;
        const float* src = g_attn + (size_t)(0 + kkb) * NG + n0 + delta;
#pragma unroll
        for (int j = 0; j < 8; ++j) {
            int jj = jb + j;
            bool ok = (unsigned)(shh[jj] + dh) < 28u &&
                      (unsigned)(sww[jj] + dw) < 28u &&
                      (unsigned)(sdd[jj] + dz) < 28u;
            bR[j] = ok ? src[jj] : 0.f;
        }
    }

    float acc[8][8];
#pragma unroll
    for (int r = 0; r < 8; ++r)
#pragma unroll
        for (int c = 0; c < 8; ++c) acc[r][c] = 0.f;

    for (int k0 = 0; k0 < 3456; k0 += 16) {
        // ---- commit prefetched regs to smem ----
        *(float4*)&As[akk0][acol0] = aR0;
        *(float4*)&As[akk1][acol1] = aR1;
#pragma unroll
        for (int j = 0; j < 8; j += 4) {
            float4 v; v.x = bR[j]; v.y = bR[j+1]; v.z = bR[j+2]; v.w = bR[j+3];
            *(float4*)&Bs[kkb][jb + j] = v;
        }
        __syncthreads();

        // ---- prefetch next chunk ----
        int k1 = k0 + 16;
        if (k1 < 3456) {
            aR0 = *(const float4*)(g_wt + (size_t)(k1 + akk0) * 128 + acol0);
            aR1 = *(const float4*)(g_wt + (size_t)(k1 + akk1) * 128 + acol1);
            int t  = k1 >> 7;
            int c0 = k1 & 127;
            int dh = t / 9 - 1;
            int r3 = t % 9;
            int dw = r3 / 3 - 1;
            int dz = r3 % 3 - 1;
            int delta = dh * 784 + dw * 28 + dz;
            const float* src = g_attn + (size_t)(c0 + kkb) * NG + n0 + delta;
#pragma unroll
            for (int j = 0; j < 8; ++j) {
                int jj = jb + j;
                bool ok = (unsigned)(shh[jj] + dh) < 28u &&
                          (unsigned)(sww[jj] + dw) < 28u &&
                          (unsigned)(sdd[jj] + dz) < 28u;
                bR[j] = ok ? src[jj] : 0.f;
            }
        }

        // ---- compute 16 kk ----
#pragma unroll
        for (int kk = 0; kk < 16; ++kk) {
            float4 a0 = *(const float4*)&As[kk][ty * 8];
            float4 a1 = *(const float4*)&As[kk][ty * 8 + 4];
            float4 b0 = *(const float4*)&Bs[kk][tx * 8];
            float4 b1 = *(const float4*)&Bs[kk][tx * 8 + 4];
            float av[8] = {a0.x, a0.y, a0.z, a0.w, a1.x, a1.y, a1.z, a1.w};
            float bv[8] = {b0.x, b0.y, b0.z, b0.w, b1.x, b1.y, b1.z, b1.w};
#pragma unroll
            for (int r = 0; r < 8; ++r)
#pragma unroll
                for (int c = 0; c < 8; ++c)
                    acc[r][c] = fmaf(av[r], bv[c], acc[r][c]);
        }
        __syncthreads();
    }

#pragma unroll
    for (int r = 0; r < 8; ++r) {
        int m = ty * 8 + r;
        float* dst = g_yb + (size_t)m * NG + n0 + tx * 8;
        float4 o0, o1;
        o0.x = acc[r][0]; o0.y = acc[r][1]; o0.z = acc[r][2]; o0.w = acc[r][3];
        o1.x = acc[r][4]; o1.y = acc[r][5]; o1.z = acc[r][6]; o1.w = acc[r][7];
        *(float4*)dst = o0;
        *(float4*)(dst + 4) = o1;
    }
}

// ===================== final: out = x + w_proj @ (attn + silu(bn(yb))) =====================
__global__ __launch_bounds__(256) void final_kernel(const float* __restrict__ x,
                                                    const float* __restrict__ w_proj,
                                                    float* __restrict__ out)
{
    __shared__ __align__(16) float As[16 * 64];
    __shared__ __align__(16) float Bs[16 * 64];
    int tid = threadIdx.x;
    int n0 = blockIdx.x * 64;
    int m0 = blockIdx.y * 64;
    int ty = tid >> 4, tx = tid & 15;
    int am = tid >> 2, ak = (tid & 3) << 2;
    int bk = tid >> 4, bc0 = (tid & 15) << 2;
    float acc[4][4];
#pragma unroll
    for (int r = 0; r < 4; ++r)
#pragma unroll
        for (int c = 0; c < 4; ++c) acc[r][c] = 0.f;

    for (int k0 = 0; k0 < 128; k0 += 16) {
        float4 av = *(const float4*)(w_proj + (size_t)(m0 + am) * 128 + k0 + ak);
        As[(ak+0)*64 + am] = av.x;
        As[(ak+1)*64 + am] = av.y;
        As[(ak+2)*64 + am] = av.z;
        As[(ak+3)*64 + am] = av.w;
        int i = k0 + bk;
        float sc = g_bn[256 + i], sh = g_bn[384 + i];
        float4 ya = *(const float4*)(g_yb   + (size_t)i * NG + n0 + bc0);
        float4 aa = *(const float4*)(g_attn + (size_t)i * NG + n0 + bc0);
        float4 tb;
        tb.x = aa.x + silu_f(fmaf(ya.x, sc, sh));
        tb.y = aa.y + silu_f(fmaf(ya.y, sc, sh));
        tb.z = aa.z + silu_f(fmaf(ya.z, sc, sh));
        tb.w = aa.w + silu_f(fmaf(ya.w, sc, sh));
        *(float4*)&Bs[bk*64 + bc0] = tb;
        __syncthreads();
#pragma unroll
        for (int kk = 0; kk < 16; ++kk) {
            float4 a4 = *(const float4*)&As[kk*64 + ty*4];
            float4 b4 = *(const float4*)&Bs[kk*64 + tx*4];
            float ar[4] = {a4.x, a4.y, a4.z, a4.w};
            float br[4] = {b4.x, b4.y, b4.z, b4.w};
#pragma unroll
            for (int r = 0; r < 4; ++r)
#pragma unroll
                for (int c = 0; c < 4; ++c)
                    acc[r][c] = fmaf(ar[r], br[c], acc[r][c]);
        }
        __syncthreads();
    }
    int b = n0 / HWD;                 // 21952 % 64 == 0 -> whole tile in one batch
    int sp = n0 - b * HWD + tx * 4;
#pragma unroll
    for (int r = 0; r < 4; ++r) {
        int m = m0 + ty*4 + r;
        size_t o = (size_t)b * BSTR + (size_t)m * HWD + sp;
        float4 xv = *(const float4*)(x + o);
        float4 ov;
        ov.x = xv.x + acc[r][0];
        ov.y = xv.y + acc[r][1];
        ov.z = xv.z + acc[r][2];
        ov.w = xv.w + acc[r][3];
        *(float4*)(out + o) = ov;
    }
}

// ===================== launch =====================
extern "C" void kernel_launch(void* const* d_in, const int* in_sizes, int n_in,
                              void* d_out, int out_size)
{
    const float* x      = (const float*)d_in[0];
    const float* g_in   = (const float*)d_in[1];
    const float* b_in   = (const float*)d_in[2];
    const float* w_qk   = (const float*)d_in[3];
    const float* w_v    = (const float*)d_in[4];
    const float* w_cl   = (const float*)d_in[5];
    const float* g_cl   = (const float*)d_in[6];
    const float* b_cl   = (const float*)d_in[7];
    const float* w_proj = (const float*)d_in[8];
    float* out = (float*)d_out;

    cudaFuncSetAttribute(attn_kernel, cudaFuncAttributeMaxDynamicSharedMemorySize,
                         ATTN_SMEM_BYTES);

    bn_stats_in_kernel<<<128, 256>>>(x, g_in, b_in);
    wt_kernel<<<1728, 256>>>(w_cl);                 // independent of bn/qkv, overlaps fine
    qkv_gemm_kernel<<<dim3(1372, 6), 256>>>(x, w_qk, w_v);
    attn_kernel<<<1024, 256, ATTN_SMEM_BYTES>>>();
    conv3d_kernel<<<686, 256>>>();
    bn_stats_y_kernel<<<128, 256>>>(g_cl, b_cl);
    final_kernel<<<dim3(1372, 2), 256>>>(x, w_proj, out);
}